// round 8
// baseline (speedup 1.0000x reference)
#include <cuda_runtime.h>
#include <math.h>

#define Nn 1024
#define C1 384
#define C2 128
#define Hh 12
#define FEATD 2112
#define NCHd 384
#define PW 1152

// ---------------- scratch (device globals; no runtime allocation) ----------------
static __device__ float g_Bcat[C1 * PW];            // assembled projection weights (384x1152)
static __device__ float g_bias[PW];
static __device__ float g_scale[PW];
static __device__ float g_P[Nn * PW];               // projections (1024x1152)
static __device__ float g_qpt[Nn * Hh * 12];        // global q points (n,h,p*3+i)
static __device__ float g_kpt[Nn * Hh * 12];
static __device__ float g_vpt[Nn * Hh * 24];
static __device__ float g_qn[Nn * Hh];              // |q_pts|^2 per (n,h)
static __device__ float g_kn[Nn * Hh];
static __device__ float g_pw[Hh];                   // sqrt(1/18)*softplus(raw)
static __device__ float g_bufA[(size_t)Hh * Nn * Nn]; // (h,q,k): cheap logits, then attn
static __device__ float g_bufB[(size_t)Nn * Nn * Hh]; // (q,k,h): full logits
static __device__ float g_out6[Nn * Hh * 40];       // [v_scalar(16) | point(24)] per (q,h)
static __device__ float g_feat[Nn * FEATD];         // assembled feature rows

// packed fp32x2 FMA: d0 += a0*b0 ; d1 += a1*b1
__device__ __forceinline__ void ffma2(float& d0, float& d1, float a0, float a1,
                                      float b0, float b1) {
    asm("{\n\t"
        ".reg .b64 ra, rb, rc;\n\t"
        "mov.b64 ra, {%2, %3};\n\t"
        "mov.b64 rb, {%4, %5};\n\t"
        "mov.b64 rc, {%0, %1};\n\t"
        "fma.rn.f32x2 rc, ra, rb, rc;\n\t"
        "mov.b64 {%0, %1}, rc;\n\t"
        "}"
        : "+f"(d0), "+f"(d1)
        : "f"(a0), "f"(a1), "f"(b0), "f"(b1));
}

// ---------------- K1: assemble weights / bias / scale / point weights ----------------
__global__ void k_setup(const float* __restrict__ wqp, const float* __restrict__ wkp,
                        const float* __restrict__ wvp, const float* __restrict__ wqs,
                        const float* __restrict__ wks, const float* __restrict__ wvs,
                        const float* __restrict__ bqp, const float* __restrict__ bkp,
                        const float* __restrict__ bvp, const float* __restrict__ rawpw) {
    int t = blockIdx.x * 256 + threadIdx.x;
    if (t < C1 * PW) {
        int c = t / PW, col = t - c * PW;
        float v;
        if (col < 144)      v = wqp[c * 144 + col];
        else if (col < 288) v = wkp[c * 144 + col - 144];
        else if (col < 576) v = wvp[c * 288 + col - 288];
        else if (col < 768) v = wqs[c * 192 + col - 576];
        else if (col < 960) v = wks[c * 192 + col - 768];
        else                v = wvs[c * 192 + col - 960];
        g_Bcat[t] = v;
    }
    if (t < PW) {
        float b = 0.f, s = 1.f;
        if (t < 144)      b = bqp[t];
        else if (t < 288) b = bkp[t - 144];
        else if (t < 576) b = bvp[t - 288];
        else if (t < 768) s = 0.25f;   // q_scalar * sqrt(1/16)
        g_bias[t] = b;
        g_scale[t] = s;
    }
    if (t < Hh) {
        float x = rawpw[t];
        float sp = (x > 20.f) ? x : log1pf(expf(x));
        g_pw[t] = sqrtf(1.f / 18.f) * sp;   // point_var = 4*9/2 = 18
    }
}

// ---------------- K2: projection GEMM 1024x1152x384 ----------------
__global__ __launch_bounds__(256) void k_proj(const float* __restrict__ A) {
    __shared__ float As[16 * 64];
    __shared__ float Bs[16 * 64];
    int n0 = blockIdx.x * 64, m0 = blockIdx.y * 64;
    int t = threadIdx.x;
    int tx = t & 15, ty = t >> 4;
    float acc[4][4] = {};
    for (int kc = 0; kc < C1; kc += 16) {
#pragma unroll
        for (int r = 0; r < 4; r++) {
            int idx = t + r * 256;
            As[(idx & 15) * 64 + (idx >> 4)] = A[(m0 + (idx >> 4)) * C1 + kc + (idx & 15)];
            Bs[(idx >> 6) * 64 + (idx & 63)] = g_Bcat[(kc + (idx >> 6)) * PW + n0 + (idx & 63)];
        }
        __syncthreads();
#pragma unroll
        for (int kk = 0; kk < 16; kk++) {
            float a[4], b[4];
#pragma unroll
            for (int i = 0; i < 4; i++) a[i] = As[kk * 64 + ty * 4 + i];
#pragma unroll
            for (int j = 0; j < 4; j++) b[j] = Bs[kk * 64 + tx * 4 + j];
#pragma unroll
            for (int i = 0; i < 4; i++)
#pragma unroll
                for (int j = 0; j < 4; j++) acc[i][j] += a[i] * b[j];
        }
        __syncthreads();
    }
#pragma unroll
    for (int i = 0; i < 4; i++) {
        int m = m0 + ty * 4 + i;
#pragma unroll
        for (int j = 0; j < 4; j++) {
            int n = n0 + tx * 4 + j;
            g_P[m * PW + n] = acc[i][j] * g_scale[n] + g_bias[n];
        }
    }
}

// ---------------- K3: rigid transform + point norms ----------------
__global__ void k_rotate(const float* __restrict__ rot, const float* __restrict__ trans) {
    int n = blockIdx.x;
    int t = threadIdx.x;
    __shared__ float R[9], T[3];
    if (t < 9) R[t] = rot[n * 9 + t];
    if (t < 3) T[t] = trans[n * 3 + t];
    __syncthreads();
    if (t < 192) {
        float l0, l1, l2;
        float* dst;
        if (t < 48) {
            int h = t >> 2, p = t & 3;
            const float* src = &g_P[n * PW + h * 12];
            l0 = src[p]; l1 = src[4 + p]; l2 = src[8 + p];
            dst = &g_qpt[(n * 12 + h) * 12 + p * 3];
        } else if (t < 96) {
            int u = t - 48; int h = u >> 2, p = u & 3;
            const float* src = &g_P[n * PW + 144 + h * 12];
            l0 = src[p]; l1 = src[4 + p]; l2 = src[8 + p];
            dst = &g_kpt[(n * 12 + h) * 12 + p * 3];
        } else {
            int u = t - 96; int h = u >> 3, p = u & 7;
            const float* src = &g_P[n * PW + 288 + h * 24];
            l0 = src[p]; l1 = src[8 + p]; l2 = src[16 + p];
            dst = &g_vpt[(n * 12 + h) * 24 + p * 3];
        }
        dst[0] = R[0] * l0 + R[1] * l1 + R[2] * l2 + T[0];
        dst[1] = R[3] * l0 + R[4] * l1 + R[5] * l2 + T[1];
        dst[2] = R[6] * l0 + R[7] * l1 + R[8] * l2 + T[2];
    }
    __syncthreads();
    if (t < 24) {
        int h = t % 12;
        const float* p = (t < 12) ? &g_qpt[(n * 12 + h) * 12] : &g_kpt[(n * 12 + h) * 12];
        float s = 0.f;
#pragma unroll
        for (int d = 0; d < 12; d++) s += p[d] * p[d];
        if (t < 12) g_qn[n * 12 + h] = s;
        else        g_kn[n * 12 + h] = s;
    }
}

// ---------------- K4: cheap logits (scalar QK + point + b2d) -> (h,q,k) ----------------
__global__ __launch_bounds__(256) void k_cheap(const float* __restrict__ b2d) {
    int k0 = blockIdx.x * 64, q0 = blockIdx.y * 64, h = blockIdx.z;
    __shared__ float qf[64 * 29];
    __shared__ float kf[64 * 29];
    __shared__ float qn_[64], kn_[64];
    int t = threadIdx.x;
    float pw = g_pw[h];
    for (int idx = t; idx < 64 * 28; idx += 256) {
        int r = idx / 28, c = idx - r * 28;
        float v, w;
        if (c < 16) {
            v = g_P[(q0 + r) * PW + 576 + h * 16 + c];
            w = g_P[(k0 + r) * PW + 768 + h * 16 + c];
        } else {
            v = g_qpt[((q0 + r) * 12 + h) * 12 + c - 16];
            w = pw * g_kpt[((k0 + r) * 12 + h) * 12 + c - 16];
        }
        qf[r * 29 + c] = v;
        kf[r * 29 + c] = w;
    }
    if (t < 64)            qn_[t] = 0.5f * pw * g_qn[(q0 + t) * 12 + h];
    else if (t < 128)      kn_[t - 64] = 0.5f * pw * g_kn[(k0 + t - 64) * 12 + h];
    __syncthreads();
    int tx = t & 15, ty = t >> 4;
    float acc[4][4] = {};
#pragma unroll
    for (int c = 0; c < 28; c++) {
        float a[4], b[4];
#pragma unroll
        for (int i = 0; i < 4; i++) a[i] = qf[(ty * 4 + i) * 29 + c];
#pragma unroll
        for (int j = 0; j < 4; j++) b[j] = kf[(tx * 4 + j) * 29 + c];
#pragma unroll
        for (int i = 0; i < 4; i++)
#pragma unroll
            for (int j = 0; j < 4; j++) acc[i][j] += a[i] * b[j];
    }
    float bb = b2d[h];
#pragma unroll
    for (int i = 0; i < 4; i++) {
        int q = q0 + ty * 4 + i;
#pragma unroll
        for (int j = 0; j < 4; j++) {
            int k = k0 + tx * 4 + j;
            g_bufA[((size_t)h << 20) + (size_t)q * 1024 + k] =
                acc[i][j] - qn_[ty * 4 + i] - kn_[tx * 4 + j] + bb;
        }
    }
}

// ---------------- K5: + inputs_2d @ w2d, writes (q,k,h) logits ----------------
// block: 512 (q,k)-pairs x 12 heads; dynamic smem: 512*33 + 384 floats
__global__ __launch_bounds__(256) void k_add2d(const float* __restrict__ in2d,
                                               const float* __restrict__ w2d) {
    extern __shared__ float dsm[];
    float* s2d = dsm;                 // [512][33]
    float* ws = dsm + 512 * 33;      // [32][12]
    int t = threadIdx.x;
    size_t pairBase = (size_t)blockIdx.x * 512;
    int ht = t & 1, kt = t >> 1;      // kt in [0,128)
    float acc[4][6];
#pragma unroll
    for (int i = 0; i < 4; i++)
#pragma unroll
        for (int j = 0; j < 6; j++) acc[i][j] = 0.f;
    for (int cc = 0; cc < 128; cc += 32) {
        for (int idx = t; idx < 384; idx += 256) ws[idx] = w2d[cc * 12 + idx];
        for (int idx = t; idx < 512 * 8; idx += 256) {
            int row = idx >> 3, c4 = idx & 7;
            const float4 v = *(const float4*)(in2d + (pairBase + row) * 128 + cc + c4 * 4);
            float* d = &s2d[row * 33 + c4 * 4];
            d[0] = v.x; d[1] = v.y; d[2] = v.z; d[3] = v.w;
        }
        __syncthreads();
#pragma unroll 8
        for (int c = 0; c < 32; c++) {
            float b0 = ws[c * 12 + ht * 6 + 0];
            float b1 = ws[c * 12 + ht * 6 + 1];
            float b2 = ws[c * 12 + ht * 6 + 2];
            float b3 = ws[c * 12 + ht * 6 + 3];
            float b4 = ws[c * 12 + ht * 6 + 4];
            float b5 = ws[c * 12 + ht * 6 + 5];
#pragma unroll
            for (int i = 0; i < 4; i++) {
                float a = s2d[(kt + 128 * i) * 33 + c];
                ffma2(acc[i][0], acc[i][1], a, a, b0, b1);
                ffma2(acc[i][2], acc[i][3], a, a, b2, b3);
                ffma2(acc[i][4], acc[i][5], a, a, b4, b5);
            }
        }
        __syncthreads();
    }
    int q = (int)(pairBase >> 10);
    int k0 = (int)(pairBase & 1023);
#pragma unroll
    for (int i = 0; i < 4; i++) {
        int k = k0 + kt + 128 * i;
        size_t kk = (size_t)q * 1024 + k;
#pragma unroll
        for (int j = 0; j < 6; j++) {
            int h = ht * 6 + j;
            float cheap = g_bufA[((size_t)h << 20) + kk];
            g_bufB[kk * 12 + h] = acc[i][j] + cheap;
        }
    }
}

// ---------------- K6: per-q masked softmax over k; attn -> (h,q,k) ----------------
// 384 threads (warp w == head w); dynamic smem 12288 floats
__global__ __launch_bounds__(384) void k_softmax(const float* __restrict__ mask) {
    extern __shared__ float sl[];
    int q = blockIdx.x;
    int t = threadIdx.x;
    float mq = mask[q];
    const float* src = g_bufB + (size_t)q * 12288;
    for (int idx = t; idx < 3072; idx += 384) {
        float4 v = *(const float4*)(src + idx * 4);
        int e = idx * 4;
        float vv[4] = {v.x, v.y, v.z, v.w};
#pragma unroll
        for (int u = 0; u < 4; u++) {
            int k = (e + u) / 12;
            float m2 = mq * mask[k];
            vv[u] = (vv[u] - 1e5f * (1.f - m2)) * 0.57735026918962576f;
        }
        float4 w = {vv[0], vv[1], vv[2], vv[3]};
        *(float4*)(sl + e) = w;
    }
    __syncthreads();
    int h = t >> 5, lane = t & 31;
    float mx = -1e30f;
    for (int k = lane; k < 1024; k += 32) mx = fmaxf(mx, sl[k * 12 + h]);
#pragma unroll
    for (int s = 16; s > 0; s >>= 1) mx = fmaxf(mx, __shfl_xor_sync(0xffffffffu, mx, s));
    float sum = 0.f;
    for (int k = lane; k < 1024; k += 32) {
        float e = __expf(sl[k * 12 + h] - mx);
        sl[k * 12 + h] = e;
        sum += e;
    }
#pragma unroll
    for (int s = 16; s > 0; s >>= 1) sum += __shfl_xor_sync(0xffffffffu, sum, s);
    float inv = 1.f / sum;
    float* dst = g_bufA + ((size_t)h << 20) + (size_t)q * 1024;
    for (int k = lane; k < 1024; k += 32) dst[k] = sl[k * 12 + h] * inv;
}

// ---------------- K7: AV (scalar + point values), per-head GEMM ----------------
__global__ __launch_bounds__(256) void k_av() {
    __shared__ __align__(16) float As[64 * 64];
    __shared__ float Bs[64 * 48];
    int h = blockIdx.y;
    int q0 = blockIdx.x * 64;
    int t = threadIdx.x;
    int tx = t & 15, ty = t >> 4;
    float acc[4][3] = {};
    for (int k0 = 0; k0 < 1024; k0 += 64) {
        const float* ab = g_bufA + ((size_t)h << 20) + (size_t)q0 * 1024 + k0;
        for (int idx = t; idx < 1024; idx += 256) {
            int r = idx >> 4, c4 = (idx & 15) * 4;
            *(float4*)(As + r * 64 + c4) = *(const float4*)(ab + (size_t)r * 1024 + c4);
        }
        for (int idx = t; idx < 64 * 48; idx += 256) {
            int kk = idx / 48, col = idx - kk * 48;
            int k = k0 + kk;
            float v = 0.f;
            if (col < 16)       v = g_P[(size_t)k * 1152 + 960 + h * 16 + col];
            else if (col < 40)  v = g_vpt[((size_t)k * 12 + h) * 24 + (col - 16)];
            Bs[kk * 48 + col] = v;
        }
        __syncthreads();
#pragma unroll 8
        for (int kk = 0; kk < 64; kk++) {
            float a[4], b[3];
#pragma unroll
            for (int i = 0; i < 4; i++) a[i] = As[(ty * 4 + i) * 64 + kk];
#pragma unroll
            for (int j = 0; j < 3; j++) b[j] = Bs[kk * 48 + tx * 3 + j];
#pragma unroll
            for (int i = 0; i < 4; i++)
#pragma unroll
                for (int j = 0; j < 3; j++) acc[i][j] += a[i] * b[j];
        }
        __syncthreads();
    }
#pragma unroll
    for (int i = 0; i < 4; i++) {
        int q = q0 + ty * 4 + i;
#pragma unroll
        for (int j = 0; j < 3; j++) {
            int col = tx * 3 + j;
            if (col < 40) g_out6[((size_t)q * 12 + h) * 40 + col] = acc[i][j];
        }
    }
}

// ---------------- K8: res_2d per q (second in2d pass) ----------------
// 256 threads = 64 c-pairs x 4 k-slices; dynamic smem 12288 floats
__global__ __launch_bounds__(256) void k_finalrow(const float* __restrict__ in2d) {
    extern __shared__ float sa[];  // attn as [k][h], then reused for reduction
    int q = blockIdx.x;
    int t = threadIdx.x;
#pragma unroll
    for (int h = 0; h < 12; h++) {
        const float* src = g_bufA + ((size_t)h << 20) + (size_t)q * 1024;
        for (int k = t; k < 1024; k += 256) sa[k * 12 + h] = src[k];
    }
    __syncthreads();
    int cp = t & 63, ks = t >> 6;
    float aX[12], aY[12];
#pragma unroll
    for (int u = 0; u < 12; u++) { aX[u] = 0.f; aY[u] = 0.f; }
    const float* base = in2d + (size_t)q * 1024 * 128 + cp * 2;
    int kEnd = ks * 256 + 256;
    for (int k = ks * 256; k < kEnd; k++) {
        float2 v = *(const float2*)(base + (size_t)k * 128);
        const float* ap = &sa[k * 12];
#pragma unroll
        for (int u = 0; u < 6; u++) {
            float2 a2 = *(const float2*)(ap + 2 * u);
            ffma2(aX[2 * u], aX[2 * u + 1], a2.x, a2.y, v.x, v.x);
            ffma2(aY[2 * u], aY[2 * u + 1], a2.x, a2.y, v.y, v.y);
        }
    }
    __syncthreads();   // everyone done reading attn from sa
    if (ks != 0) {
        float* d = sa + (size_t)((ks - 1) * 64 + cp) * 24;
#pragma unroll
        for (int u = 0; u < 12; u++) { d[u] = aX[u]; d[12 + u] = aY[u]; }
    }
    __syncthreads();
    if (ks == 0) {
#pragma unroll
        for (int s = 0; s < 3; s++) {
            const float* d = sa + (size_t)(s * 64 + cp) * 24;
#pragma unroll
            for (int u = 0; u < 12; u++) { aX[u] += d[u]; aY[u] += d[12 + u]; }
        }
        float* f = g_feat + (size_t)q * 2112 + 576;
#pragma unroll
        for (int hh = 0; hh < 12; hh++) {
            f[hh * 128 + 2 * cp]     = aX[hh];
            f[hh * 128 + 2 * cp + 1] = aY[hh];
        }
    }
}

// ---------------- K9: inverse rigid, norms, feature assembly ----------------
__global__ void k_post(const float* __restrict__ rot, const float* __restrict__ trans) {
    int q = blockIdx.x;
    int t = threadIdx.x;   // 288
    float* f = g_feat + (size_t)q * 2112;
    const float* o6 = g_out6 + (size_t)q * 12 * 40;
    if (t < 96) {
        int h = t >> 3, p = t & 7;
        const float* g = o6 + h * 40 + 16 + p * 3;
        float g0 = g[0] - trans[q * 3 + 0];
        float g1 = g[1] - trans[q * 3 + 1];
        float g2 = g[2] - trans[q * 3 + 2];
        const float* R = rot + q * 9;
        float l0 = R[0] * g0 + R[3] * g1 + R[6] * g2;
        float l1 = R[1] * g0 + R[4] * g1 + R[7] * g2;
        float l2 = R[2] * g0 + R[5] * g1 + R[8] * g2;
        int idx = h * 8 + p;
        f[192 + idx] = l0;
        f[288 + idx] = l1;
        f[384 + idx] = l2;
        f[480 + idx] = sqrtf(fmaxf(l0 * l0 + l1 * l1 + l2 * l2, 1e-16f));
    } else if (t < 288) {
        int idx = t - 96;           // 0..191
        int h = idx >> 4, s = idx & 15;
        f[idx] = o6[h * 40 + s];
    }
}

// ---------------- K10: output GEMM 1024x384x2112 ----------------
__global__ __launch_bounds__(256) void k_out(const float* __restrict__ wout,
                                             const float* __restrict__ bout,
                                             float* __restrict__ out) {
    __shared__ float As[16 * 64];
    __shared__ float Bs[16 * 64];
    int n0 = blockIdx.x * 64, m0 = blockIdx.y * 64;
    int t = threadIdx.x;
    int tx = t & 15, ty = t >> 4;
    float acc[4][4] = {};
    for (int kc = 0; kc < FEATD; kc += 16) {
#pragma unroll
        for (int r = 0; r < 4; r++) {
            int idx = t + r * 256;
            As[(idx & 15) * 64 + (idx >> 4)] =
                g_feat[(size_t)(m0 + (idx >> 4)) * FEATD + kc + (idx & 15)];
            Bs[(idx >> 6) * 64 + (idx & 63)] =
                wout[(size_t)(kc + (idx >> 6)) * NCHd + n0 + (idx & 63)];
        }
        __syncthreads();
#pragma unroll
        for (int kk = 0; kk < 16; kk++) {
            float a[4], b[4];
#pragma unroll
            for (int i = 0; i < 4; i++) a[i] = As[kk * 64 + ty * 4 + i];
#pragma unroll
            for (int j = 0; j < 4; j++) b[j] = Bs[kk * 64 + tx * 4 + j];
#pragma unroll
            for (int i = 0; i < 4; i++)
#pragma unroll
                for (int j = 0; j < 4; j++) acc[i][j] += a[i] * b[j];
        }
        __syncthreads();
    }
#pragma unroll
    for (int i = 0; i < 4; i++) {
        int m = m0 + ty * 4 + i;
#pragma unroll
        for (int j = 0; j < 4; j++) {
            int n = n0 + tx * 4 + j;
            out[(size_t)m * NCHd + n] = acc[i][j] + bout[n];
        }
    }
}

// ---------------- launch ----------------
extern "C" void kernel_launch(void* const* d_in, const int* in_sizes, int n_in,
                              void* d_out, int out_size) {
    const float* inputs_1d = (const float*)d_in[0];
    const float* inputs_2d = (const float*)d_in[1];
    const float* mask      = (const float*)d_in[2];
    const float* rot       = (const float*)d_in[3];
    const float* trans     = (const float*)d_in[4];
    const float* rawpw     = (const float*)d_in[5];
    const float* wq_point  = (const float*)d_in[6];
    const float* bq_point  = (const float*)d_in[7];
    const float* wk_point  = (const float*)d_in[8];
    const float* bk_point  = (const float*)d_in[9];
    const float* wv_point  = (const float*)d_in[10];
    const float* bv_point  = (const float*)d_in[11];
    const float* wq_scalar = (const float*)d_in[12];
    const float* wk_scalar = (const float*)d_in[13];
    const float* wv_scalar = (const float*)d_in[14];
    const float* w2d       = (const float*)d_in[15];
    const float* b2d       = (const float*)d_in[16];
    const float* wout      = (const float*)d_in[17];
    const float* bout      = (const float*)d_in[18];
    float* out = (float*)d_out;

    cudaFuncSetAttribute(k_add2d, cudaFuncAttributeMaxDynamicSharedMemorySize,
                         (512 * 33 + 384) * 4);
    cudaFuncSetAttribute(k_softmax, cudaFuncAttributeMaxDynamicSharedMemorySize,
                         12288 * 4);
    cudaFuncSetAttribute(k_finalrow, cudaFuncAttributeMaxDynamicSharedMemorySize,
                         12288 * 4);

    k_setup<<<(C1 * PW + 255) / 256, 256>>>(wq_point, wk_point, wv_point,
                                            wq_scalar, wk_scalar, wv_scalar,
                                            bq_point, bk_point, bv_point, rawpw);
    k_proj<<<dim3(PW / 64, Nn / 64), 256>>>(inputs_1d);
    k_rotate<<<Nn, 256>>>(rot, trans);
    k_cheap<<<dim3(16, 16, 12), 256>>>(b2d);
    k_add2d<<<2048, 256, (512 * 33 + 384) * 4>>>(inputs_2d, w2d);
    k_softmax<<<Nn, 384, 12288 * 4>>>(mask);
    k_av<<<dim3(16, 12), 256>>>();
    k_finalrow<<<Nn, 256, 12288 * 4>>>(inputs_2d);
    k_post<<<Nn, 288>>>(rot, trans);
    k_out<<<dim3(NCHd / 64, Nn / 64), 256>>>(wout, bout, out);
}

// round 9
// speedup vs baseline: 1.0926x; 1.0926x over previous
#include <cuda_runtime.h>
#include <math.h>

#define Nn 1024
#define C1 384
#define C2 128
#define Hh 12
#define FEATD 2112
#define NCHd 384
#define PW 1152
#define LPAD 17

// ---------------- scratch (device globals; no runtime allocation) ----------------
static __device__ float g_Bcat[C1 * PW];            // assembled projection weights (384x1152)
static __device__ float g_bias[PW];
static __device__ float g_scale[PW];
static __device__ float g_P[Nn * PW];               // projections (1024x1152)
static __device__ float g_qpt[Nn * Hh * 12];        // global q points (n,h,p*3+i)
static __device__ float g_kpt[Nn * Hh * 12];
static __device__ float g_vpt[Nn * Hh * 24];
static __device__ float g_qn[Nn * Hh];              // |q_pts|^2 per (n,h)
static __device__ float g_kn[Nn * Hh];
static __device__ float g_pw[Hh];                   // sqrt(1/18)*softplus(raw)
static __device__ float g_bufA[(size_t)Hh * Nn * Nn]; // (h,q,k): cheap logits, then attn
static __device__ float g_out6[Nn * Hh * 40];       // [v_scalar(16) | point(24)] per (q,h)
static __device__ float g_feat[Nn * FEATD];         // assembled feature rows

// packed fp32x2 FMA: d0 += a0*b0 ; d1 += a1*b1
__device__ __forceinline__ void ffma2(float& d0, float& d1, float a0, float a1,
                                      float b0, float b1) {
    asm("{\n\t"
        ".reg .b64 ra, rb, rc;\n\t"
        "mov.b64 ra, {%2, %3};\n\t"
        "mov.b64 rb, {%4, %5};\n\t"
        "mov.b64 rc, {%0, %1};\n\t"
        "fma.rn.f32x2 rc, ra, rb, rc;\n\t"
        "mov.b64 {%0, %1}, rc;\n\t"
        "}"
        : "+f"(d0), "+f"(d1)
        : "f"(a0), "f"(a1), "f"(b0), "f"(b1));
}

// ---------------- K1: assemble weights / bias / scale / point weights ----------------
__global__ void k_setup(const float* __restrict__ wqp, const float* __restrict__ wkp,
                        const float* __restrict__ wvp, const float* __restrict__ wqs,
                        const float* __restrict__ wks, const float* __restrict__ wvs,
                        const float* __restrict__ bqp, const float* __restrict__ bkp,
                        const float* __restrict__ bvp, const float* __restrict__ rawpw) {
    int t = blockIdx.x * 256 + threadIdx.x;
    if (t < C1 * PW) {
        int c = t / PW, col = t - c * PW;
        float v;
        if (col < 144)      v = wqp[c * 144 + col];
        else if (col < 288) v = wkp[c * 144 + col - 144];
        else if (col < 576) v = wvp[c * 288 + col - 288];
        else if (col < 768) v = wqs[c * 192 + col - 576];
        else if (col < 960) v = wks[c * 192 + col - 768];
        else                v = wvs[c * 192 + col - 960];
        g_Bcat[t] = v;
    }
    if (t < PW) {
        float b = 0.f, s = 1.f;
        if (t < 144)      b = bqp[t];
        else if (t < 288) b = bkp[t - 144];
        else if (t < 576) b = bvp[t - 288];
        else if (t < 768) s = 0.25f;   // q_scalar * sqrt(1/16)
        g_bias[t] = b;
        g_scale[t] = s;
    }
    if (t < Hh) {
        float x = rawpw[t];
        float sp = (x > 20.f) ? x : log1pf(expf(x));
        g_pw[t] = sqrtf(1.f / 18.f) * sp;   // point_var = 4*9/2 = 18
    }
}

// ---------------- K2: projection GEMM 1024x1152x384 ----------------
__global__ __launch_bounds__(256) void k_proj(const float* __restrict__ A) {
    __shared__ __align__(16) float As[16 * 64];
    __shared__ __align__(16) float Bs[16 * 64];
    int n0 = blockIdx.x * 64, m0 = blockIdx.y * 64;
    int t = threadIdx.x;
    int tx = t & 15, ty = t >> 4;
    float acc[4][4] = {};
    for (int kc = 0; kc < C1; kc += 16) {
#pragma unroll
        for (int r = 0; r < 4; r++) {
            int idx = t + r * 256;
            As[(idx & 15) * 64 + (idx >> 4)] = A[(m0 + (idx >> 4)) * C1 + kc + (idx & 15)];
            Bs[(idx >> 6) * 64 + (idx & 63)] = g_Bcat[(kc + (idx >> 6)) * PW + n0 + (idx & 63)];
        }
        __syncthreads();
#pragma unroll
        for (int kk = 0; kk < 16; kk++) {
            float4 a4 = *(const float4*)(As + kk * 64 + ty * 4);
            float4 b4 = *(const float4*)(Bs + kk * 64 + tx * 4);
            ffma2(acc[0][0], acc[0][1], a4.x, a4.x, b4.x, b4.y);
            ffma2(acc[0][2], acc[0][3], a4.x, a4.x, b4.z, b4.w);
            ffma2(acc[1][0], acc[1][1], a4.y, a4.y, b4.x, b4.y);
            ffma2(acc[1][2], acc[1][3], a4.y, a4.y, b4.z, b4.w);
            ffma2(acc[2][0], acc[2][1], a4.z, a4.z, b4.x, b4.y);
            ffma2(acc[2][2], acc[2][3], a4.z, a4.z, b4.z, b4.w);
            ffma2(acc[3][0], acc[3][1], a4.w, a4.w, b4.x, b4.y);
            ffma2(acc[3][2], acc[3][3], a4.w, a4.w, b4.z, b4.w);
        }
        __syncthreads();
    }
#pragma unroll
    for (int i = 0; i < 4; i++) {
        int m = m0 + ty * 4 + i;
#pragma unroll
        for (int j = 0; j < 4; j++) {
            int n = n0 + tx * 4 + j;
            g_P[m * PW + n] = acc[i][j] * g_scale[n] + g_bias[n];
        }
    }
}

// ---------------- K3: rigid transform + point norms ----------------
__global__ void k_rotate(const float* __restrict__ rot, const float* __restrict__ trans) {
    int n = blockIdx.x;
    int t = threadIdx.x;
    __shared__ float R[9], T[3];
    if (t < 9) R[t] = rot[n * 9 + t];
    if (t < 3) T[t] = trans[n * 3 + t];
    __syncthreads();
    if (t < 192) {
        float l0, l1, l2;
        float* dst;
        if (t < 48) {
            int h = t >> 2, p = t & 3;
            const float* src = &g_P[n * PW + h * 12];
            l0 = src[p]; l1 = src[4 + p]; l2 = src[8 + p];
            dst = &g_qpt[(n * 12 + h) * 12 + p * 3];
        } else if (t < 96) {
            int u = t - 48; int h = u >> 2, p = u & 3;
            const float* src = &g_P[n * PW + 144 + h * 12];
            l0 = src[p]; l1 = src[4 + p]; l2 = src[8 + p];
            dst = &g_kpt[(n * 12 + h) * 12 + p * 3];
        } else {
            int u = t - 96; int h = u >> 3, p = u & 7;
            const float* src = &g_P[n * PW + 288 + h * 24];
            l0 = src[p]; l1 = src[8 + p]; l2 = src[16 + p];
            dst = &g_vpt[(n * 12 + h) * 24 + p * 3];
        }
        dst[0] = R[0] * l0 + R[1] * l1 + R[2] * l2 + T[0];
        dst[1] = R[3] * l0 + R[4] * l1 + R[5] * l2 + T[1];
        dst[2] = R[6] * l0 + R[7] * l1 + R[8] * l2 + T[2];
    }
    __syncthreads();
    if (t < 24) {
        int h = t % 12;
        const float* p = (t < 12) ? &g_qpt[(n * 12 + h) * 12] : &g_kpt[(n * 12 + h) * 12];
        float s = 0.f;
#pragma unroll
        for (int d = 0; d < 12; d++) s += p[d] * p[d];
        if (t < 12) g_qn[n * 12 + h] = s;
        else        g_kn[n * 12 + h] = s;
    }
}

// ---------------- K4: cheap logits (scalar QK + point + b2d) -> (h,q,k) ----------------
__global__ __launch_bounds__(256) void k_cheap(const float* __restrict__ b2d) {
    int k0 = blockIdx.x * 64, q0 = blockIdx.y * 64, h = blockIdx.z;
    __shared__ __align__(16) float qf[28 * 64];   // [c][r]
    __shared__ __align__(16) float kf[28 * 64];
    __shared__ float qn_[64], kn_[64];
    int t = threadIdx.x;
    float pw = g_pw[h];
    // fill: 64 rows x 8 groups (g==7 unused); g<4: scalar float4, g in 4..6: point float4
    for (int u = t; u < 512; u += 256) {
        int r = u >> 3, g = u & 7;
        if (g < 4) {
            float4 v = *(const float4*)(&g_P[(size_t)(q0 + r) * PW + 576 + h * 16 + g * 4]);
            qf[(g * 4 + 0) * 64 + r] = v.x; qf[(g * 4 + 1) * 64 + r] = v.y;
            qf[(g * 4 + 2) * 64 + r] = v.z; qf[(g * 4 + 3) * 64 + r] = v.w;
            float4 w = *(const float4*)(&g_P[(size_t)(k0 + r) * PW + 768 + h * 16 + g * 4]);
            kf[(g * 4 + 0) * 64 + r] = w.x; kf[(g * 4 + 1) * 64 + r] = w.y;
            kf[(g * 4 + 2) * 64 + r] = w.z; kf[(g * 4 + 3) * 64 + r] = w.w;
        } else if (g < 7) {
            int pc = 16 + (g - 4) * 4;
            float4 v = *(const float4*)(&g_qpt[(((size_t)(q0 + r)) * 12 + h) * 12 + (g - 4) * 4]);
            qf[(pc + 0) * 64 + r] = v.x; qf[(pc + 1) * 64 + r] = v.y;
            qf[(pc + 2) * 64 + r] = v.z; qf[(pc + 3) * 64 + r] = v.w;
            float4 w = *(const float4*)(&g_kpt[(((size_t)(k0 + r)) * 12 + h) * 12 + (g - 4) * 4]);
            kf[(pc + 0) * 64 + r] = pw * w.x; kf[(pc + 1) * 64 + r] = pw * w.y;
            kf[(pc + 2) * 64 + r] = pw * w.z; kf[(pc + 3) * 64 + r] = pw * w.w;
        }
    }
    if (t < 64)            qn_[t] = 0.5f * pw * g_qn[(q0 + t) * 12 + h];
    else if (t < 128)      kn_[t - 64] = 0.5f * pw * g_kn[(k0 + t - 64) * 12 + h];
    __syncthreads();
    int tx = t & 15, ty = t >> 4;
    float acc[4][4] = {};
#pragma unroll
    for (int c = 0; c < 28; c++) {
        float4 a4 = *(const float4*)(qf + c * 64 + ty * 4);
        float4 b4 = *(const float4*)(kf + c * 64 + tx * 4);
        ffma2(acc[0][0], acc[0][1], a4.x, a4.x, b4.x, b4.y);
        ffma2(acc[0][2], acc[0][3], a4.x, a4.x, b4.z, b4.w);
        ffma2(acc[1][0], acc[1][1], a4.y, a4.y, b4.x, b4.y);
        ffma2(acc[1][2], acc[1][3], a4.y, a4.y, b4.z, b4.w);
        ffma2(acc[2][0], acc[2][1], a4.z, a4.z, b4.x, b4.y);
        ffma2(acc[2][2], acc[2][3], a4.z, a4.z, b4.z, b4.w);
        ffma2(acc[3][0], acc[3][1], a4.w, a4.w, b4.x, b4.y);
        ffma2(acc[3][2], acc[3][3], a4.w, a4.w, b4.z, b4.w);
    }
    float bb = b2d[h];
#pragma unroll
    for (int i = 0; i < 4; i++) {
        int q = q0 + ty * 4 + i;
#pragma unroll
        for (int j = 0; j < 4; j++) {
            int k = k0 + tx * 4 + j;
            g_bufA[((size_t)h << 20) + (size_t)q * 1024 + k] =
                acc[i][j] - qn_[ty * 4 + i] - kn_[tx * 4 + j] + bb;
        }
    }
}

// ---------------- K5: fused inputs_2d projection + cheap-add + mask + softmax ----------------
// one block per q; thread t owns k in {t, t+256, t+512, t+768}; attn -> g_bufA (h,q,k)
__global__ __launch_bounds__(256) void k_logits(const float* __restrict__ in2d,
                                                const float* __restrict__ w2d,
                                                const float* __restrict__ mask) {
    extern __shared__ float dsm[];
    float* s2d = dsm;                 // [1024][LPAD]
    float* ws  = dsm + 1024 * LPAD;   // 192 floats (w2d chunk); reused as red[96]
    int q = blockIdx.x, t = threadIdx.x;
    float acc[4][12];
#pragma unroll
    for (int s = 0; s < 4; s++)
#pragma unroll
        for (int h = 0; h < 12; h++) acc[s][h] = 0.f;
    const float* inrow = in2d + (size_t)q * 131072;
    for (int c0 = 0; c0 < 128; c0 += 16) {
        if (t < 192) ws[t] = w2d[c0 * 12 + t];
#pragma unroll
        for (int it = 0; it < 16; it++) {
            int idx = t + it * 256;
            int row = idx >> 2, cq = (idx & 3) * 4;
            float4 v = *(const float4*)(inrow + row * 128 + c0 + cq);
            float* d = s2d + row * LPAD + cq;
            d[0] = v.x; d[1] = v.y; d[2] = v.z; d[3] = v.w;
        }
        __syncthreads();
#pragma unroll
        for (int c = 0; c < 16; c++) {
            float b[12];
#pragma unroll
            for (int u = 0; u < 6; u++) {
                float2 bv = *(const float2*)(ws + c * 12 + u * 2);
                b[2 * u] = bv.x; b[2 * u + 1] = bv.y;
            }
#pragma unroll
            for (int s = 0; s < 4; s++) {
                float a = s2d[(t + s * 256) * LPAD + c];
#pragma unroll
                for (int u = 0; u < 6; u++)
                    ffma2(acc[s][2 * u], acc[s][2 * u + 1], a, a, b[2 * u], b[2 * u + 1]);
            }
        }
        __syncthreads();
    }
    // ---- epilogue: add cheap, mask, scale ----
    float* red = ws;
    const float scale = 0.57735026918962576f;
    float mq = mask[q];
    float pen[4];
#pragma unroll
    for (int s = 0; s < 4; s++) pen[s] = -1e5f * (1.f - mq * mask[t + s * 256]);
#pragma unroll
    for (int h = 0; h < 12; h++) {
        size_t off = ((size_t)h << 20) + ((size_t)q << 10) + t;
#pragma unroll
        for (int s = 0; s < 4; s++) {
            float ch = g_bufA[off + s * 256];
            acc[s][h] = (acc[s][h] + ch + pen[s]) * scale;
        }
    }
    // ---- softmax over k (block-wide per h) ----
    int w = t >> 5, lane = t & 31;
#pragma unroll
    for (int h = 0; h < 12; h++) {
        float m = fmaxf(fmaxf(acc[0][h], acc[1][h]), fmaxf(acc[2][h], acc[3][h]));
#pragma unroll
        for (int s = 16; s; s >>= 1) m = fmaxf(m, __shfl_xor_sync(0xffffffffu, m, s));
        if (lane == 0) red[w * 12 + h] = m;
    }
    __syncthreads();
    float hm[12];
#pragma unroll
    for (int h = 0; h < 12; h++) {
        float m = red[h];
#pragma unroll
        for (int w2 = 1; w2 < 8; w2++) m = fmaxf(m, red[w2 * 12 + h]);
        hm[h] = m;
    }
    __syncthreads();
#pragma unroll
    for (int h = 0; h < 12; h++) {
        float s0 = 0.f;
#pragma unroll
        for (int s = 0; s < 4; s++) {
            acc[s][h] = __expf(acc[s][h] - hm[h]);
            s0 += acc[s][h];
        }
#pragma unroll
        for (int s = 16; s; s >>= 1) s0 += __shfl_xor_sync(0xffffffffu, s0, s);
        if (lane == 0) red[w * 12 + h] = s0;
    }
    __syncthreads();
#pragma unroll
    for (int h = 0; h < 12; h++) {
        float tot = red[h];
#pragma unroll
        for (int w2 = 1; w2 < 8; w2++) tot += red[w2 * 12 + h];
        float inv = 1.f / tot;
        size_t off = ((size_t)h << 20) + ((size_t)q << 10) + t;
#pragma unroll
        for (int s = 0; s < 4; s++) g_bufA[off + s * 256] = acc[s][h] * inv;
    }
}

// ---------------- K7: AV (scalar + point values), per-head GEMM ----------------
__global__ __launch_bounds__(256) void k_av() {
    __shared__ __align__(16) float As[64 * 64];   // [kk][r]
    __shared__ float Bs[64 * 48];
    int h = blockIdx.y;
    int q0 = blockIdx.x * 64;
    int t = threadIdx.x;
    int tx = t & 15, ty = t >> 4;
    float acc[4][3] = {};
    for (int k0 = 0; k0 < 1024; k0 += 64) {
        const float* ab = g_bufA + ((size_t)h << 20) + (size_t)q0 * 1024 + k0;
        for (int idx = t; idx < 1024; idx += 256) {
            int r = idx >> 4, c4 = (idx & 15) * 4;
            float4 v = *(const float4*)(ab + (size_t)r * 1024 + c4);
            As[(c4 + 0) * 64 + r] = v.x; As[(c4 + 1) * 64 + r] = v.y;
            As[(c4 + 2) * 64 + r] = v.z; As[(c4 + 3) * 64 + r] = v.w;
        }
        for (int idx = t; idx < 64 * 48; idx += 256) {
            int kk = idx / 48, col = idx - kk * 48;
            int k = k0 + kk;
            float v = 0.f;
            if (col < 16)       v = g_P[(size_t)k * 1152 + 960 + h * 16 + col];
            else if (col < 40)  v = g_vpt[((size_t)k * 12 + h) * 24 + (col - 16)];
            Bs[kk * 48 + col] = v;
        }
        __syncthreads();
#pragma unroll 8
        for (int kk = 0; kk < 64; kk++) {
            float4 a4 = *(const float4*)(As + kk * 64 + ty * 4);
            float b0 = Bs[kk * 48 + tx * 3 + 0];
            float b1 = Bs[kk * 48 + tx * 3 + 1];
            float b2 = Bs[kk * 48 + tx * 3 + 2];
            ffma2(acc[0][0], acc[1][0], a4.x, a4.y, b0, b0);
            ffma2(acc[2][0], acc[3][0], a4.z, a4.w, b0, b0);
            ffma2(acc[0][1], acc[1][1], a4.x, a4.y, b1, b1);
            ffma2(acc[2][1], acc[3][1], a4.z, a4.w, b1, b1);
            ffma2(acc[0][2], acc[1][2], a4.x, a4.y, b2, b2);
            ffma2(acc[2][2], acc[3][2], a4.z, a4.w, b2, b2);
        }
        __syncthreads();
    }
#pragma unroll
    for (int i = 0; i < 4; i++) {
        int q = q0 + ty * 4 + i;
#pragma unroll
        for (int j = 0; j < 3; j++) {
            int col = tx * 3 + j;
            if (col < 40) g_out6[((size_t)q * 12 + h) * 40 + col] = acc[i][j];
        }
    }
}

// ---------------- K8: res_2d per q (second in2d pass) ----------------
// 256 threads = 64 c-pairs x 4 k-slices; dynamic smem 12288 floats (attn planes)
__global__ __launch_bounds__(256) void k_final(const float* __restrict__ in2d) {
    extern __shared__ float sa[];   // [h][1024]
    int q = blockIdx.x;
    int t = threadIdx.x;
#pragma unroll
    for (int h = 0; h < 12; h++) {
        float4 v = *(const float4*)(g_bufA + ((size_t)h << 20) + ((size_t)q << 10) + t * 4);
        *(float4*)(sa + h * 1024 + t * 4) = v;
    }
    __syncthreads();
    int cp = t & 63, ks = t >> 6;
    float aX[12], aY[12];
#pragma unroll
    for (int u = 0; u < 12; u++) { aX[u] = 0.f; aY[u] = 0.f; }
    const float* base = in2d + (size_t)q * 131072 + cp * 2;
    int kbase = ks * 256;
    for (int kt = 0; kt < 64; kt++) {
        int k0 = kbase + kt * 4;
        float2 v0 = *(const float2*)(base + (size_t)(k0 + 0) * 128);
        float2 v1 = *(const float2*)(base + (size_t)(k0 + 1) * 128);
        float2 v2 = *(const float2*)(base + (size_t)(k0 + 2) * 128);
        float2 v3 = *(const float2*)(base + (size_t)(k0 + 3) * 128);
#pragma unroll
        for (int u = 0; u < 6; u++) {
            float4 a0 = *(const float4*)(sa + (2 * u) * 1024 + k0);
            float4 a1 = *(const float4*)(sa + (2 * u + 1) * 1024 + k0);
            ffma2(aX[2 * u], aX[2 * u + 1], a0.x, a1.x, v0.x, v0.x);
            ffma2(aY[2 * u], aY[2 * u + 1], a0.x, a1.x, v0.y, v0.y);
            ffma2(aX[2 * u], aX[2 * u + 1], a0.y, a1.y, v1.x, v1.x);
            ffma2(aY[2 * u], aY[2 * u + 1], a0.y, a1.y, v1.y, v1.y);
            ffma2(aX[2 * u], aX[2 * u + 1], a0.z, a1.z, v2.x, v2.x);
            ffma2(aY[2 * u], aY[2 * u + 1], a0.z, a1.z, v2.y, v2.y);
            ffma2(aX[2 * u], aX[2 * u + 1], a0.w, a1.w, v3.x, v3.x);
            ffma2(aY[2 * u], aY[2 * u + 1], a0.w, a1.w, v3.y, v3.y);
        }
    }
    __syncthreads();   // everyone done reading attn from sa
    if (ks != 0) {
        float* d = sa + (size_t)((ks - 1) * 64 + cp) * 24;
#pragma unroll
        for (int u = 0; u < 12; u++) { d[u] = aX[u]; d[12 + u] = aY[u]; }
    }
    __syncthreads();
    if (ks == 0) {
#pragma unroll
        for (int s = 0; s < 3; s++) {
            const float* d = sa + (size_t)(s * 64 + cp) * 24;
#pragma unroll
            for (int u = 0; u < 12; u++) { aX[u] += d[u]; aY[u] += d[12 + u]; }
        }
        float* f = g_feat + (size_t)q * 2112 + 576;
#pragma unroll
        for (int hh = 0; hh < 12; hh++) {
            f[hh * 128 + 2 * cp]     = aX[hh];
            f[hh * 128 + 2 * cp + 1] = aY[hh];
        }
    }
}

// ---------------- K9: inverse rigid, norms, feature assembly ----------------
__global__ void k_post(const float* __restrict__ rot, const float* __restrict__ trans) {
    int q = blockIdx.x;
    int t = threadIdx.x;   // 288
    float* f = g_feat + (size_t)q * 2112;
    const float* o6 = g_out6 + (size_t)q * 12 * 40;
    if (t < 96) {
        int h = t >> 3, p = t & 7;
        const float* g = o6 + h * 40 + 16 + p * 3;
        float g0 = g[0] - trans[q * 3 + 0];
        float g1 = g[1] - trans[q * 3 + 1];
        float g2 = g[2] - trans[q * 3 + 2];
        const float* R = rot + q * 9;
        float l0 = R[0] * g0 + R[3] * g1 + R[6] * g2;
        float l1 = R[1] * g0 + R[4] * g1 + R[7] * g2;
        float l2 = R[2] * g0 + R[5] * g1 + R[8] * g2;
        int idx = h * 8 + p;
        f[192 + idx] = l0;
        f[288 + idx] = l1;
        f[384 + idx] = l2;
        f[480 + idx] = sqrtf(fmaxf(l0 * l0 + l1 * l1 + l2 * l2, 1e-16f));
    } else if (t < 288) {
        int idx = t - 96;           // 0..191
        int h = idx >> 4, s = idx & 15;
        f[idx] = o6[h * 40 + s];
    }
}

// ---------------- K10: output GEMM 1024x384x2112 ----------------
__global__ __launch_bounds__(256) void k_out(const float* __restrict__ wout,
                                             const float* __restrict__ bout,
                                             float* __restrict__ out) {
    __shared__ __align__(16) float As[16 * 64];
    __shared__ __align__(16) float Bs[16 * 64];
    int n0 = blockIdx.x * 64, m0 = blockIdx.y * 64;
    int t = threadIdx.x;
    int tx = t & 15, ty = t >> 4;
    float acc[4][4] = {};
    for (int kc = 0; kc < FEATD; kc += 16) {
#pragma unroll
        for (int r = 0; r < 4; r++) {
            int idx = t + r * 256;
            As[(idx & 15) * 64 + (idx >> 4)] =
                g_feat[(size_t)(m0 + (idx >> 4)) * FEATD + kc + (idx & 15)];
            Bs[(idx >> 6) * 64 + (idx & 63)] =
                wout[(size_t)(kc + (idx >> 6)) * NCHd + n0 + (idx & 63)];
        }
        __syncthreads();
#pragma unroll
        for (int kk = 0; kk < 16; kk++) {
            float4 a4 = *(const float4*)(As + kk * 64 + ty * 4);
            float4 b4 = *(const float4*)(Bs + kk * 64 + tx * 4);
            ffma2(acc[0][0], acc[0][1], a4.x, a4.x, b4.x, b4.y);
            ffma2(acc[0][2], acc[0][3], a4.x, a4.x, b4.z, b4.w);
            ffma2(acc[1][0], acc[1][1], a4.y, a4.y, b4.x, b4.y);
            ffma2(acc[1][2], acc[1][3], a4.y, a4.y, b4.z, b4.w);
            ffma2(acc[2][0], acc[2][1], a4.z, a4.z, b4.x, b4.y);
            ffma2(acc[2][2], acc[2][3], a4.z, a4.z, b4.z, b4.w);
            ffma2(acc[3][0], acc[3][1], a4.w, a4.w, b4.x, b4.y);
            ffma2(acc[3][2], acc[3][3], a4.w, a4.w, b4.z, b4.w);
        }
        __syncthreads();
    }
#pragma unroll
    for (int i = 0; i < 4; i++) {
        int m = m0 + ty * 4 + i;
#pragma unroll
        for (int j = 0; j < 4; j++) {
            int n = n0 + tx * 4 + j;
            out[(size_t)m * NCHd + n] = acc[i][j] + bout[n];
        }
    }
}

// ---------------- launch ----------------
extern "C" void kernel_launch(void* const* d_in, const int* in_sizes, int n_in,
                              void* d_out, int out_size) {
    const float* inputs_1d = (const float*)d_in[0];
    const float* inputs_2d = (const float*)d_in[1];
    const float* mask      = (const float*)d_in[2];
    const float* rot       = (const float*)d_in[3];
    const float* trans     = (const float*)d_in[4];
    const float* rawpw     = (const float*)d_in[5];
    const float* wq_point  = (const float*)d_in[6];
    const float* bq_point  = (const float*)d_in[7];
    const float* wk_point  = (const float*)d_in[8];
    const float* bk_point  = (const float*)d_in[9];
    const float* wv_point  = (const float*)d_in[10];
    const float* bv_point  = (const float*)d_in[11];
    const float* wq_scalar = (const float*)d_in[12];
    const float* wk_scalar = (const float*)d_in[13];
    const float* wv_scalar = (const float*)d_in[14];
    const float* w2d       = (const float*)d_in[15];
    const float* b2d       = (const float*)d_in[16];
    const float* wout      = (const float*)d_in[17];
    const float* bout      = (const float*)d_in[18];
    float* out = (float*)d_out;

    const int smem_logits = (1024 * LPAD + 192) * 4;   // 70400 B
    const int smem_final  = 12288 * 4;                 // 49152 B
    cudaFuncSetAttribute(k_logits, cudaFuncAttributeMaxDynamicSharedMemorySize, smem_logits);
    cudaFuncSetAttribute(k_final,  cudaFuncAttributeMaxDynamicSharedMemorySize, smem_final);

    k_setup<<<(C1 * PW + 255) / 256, 256>>>(wq_point, wk_point, wv_point,
                                            wq_scalar, wk_scalar, wv_scalar,
                                            bq_point, bk_point, bv_point, rawpw);
    k_proj<<<dim3(PW / 64, Nn / 64), 256>>>(inputs_1d);
    k_rotate<<<Nn, 256>>>(rot, trans);
    k_cheap<<<dim3(16, 16, 12), 256>>>(b2d);
    k_logits<<<Nn, 256, smem_logits>>>(inputs_2d, w2d, mask);
    k_av<<<dim3(16, 12), 256>>>();
    k_final<<<Nn, 256, smem_final>>>(inputs_2d);
    k_post<<<Nn, 288>>>(rot, trans);
    k_out<<<dim3(NCHd / 64, Nn / 64), 256>>>(wout, bout, out);
}